// round 10
// baseline (speedup 1.0000x reference)
#include <cuda_runtime.h>

#define BB 8
#define PP 12000
#define NP (BB*PP)
#define XN_ 144
#define CELLS (144*144)
#define NC (BB*CELLS)
#define NBLK 304
#define NWARPS (NBLK*8)

// per-(batch,cell) winning pillar index (last write wins == max p)
__device__ int g_winner[NC];
// dense per-cell features, channel-major: g_feat[(b*CELLS+cell)*64 + c]
__device__ float g_feat[(size_t)NC * 64];

__global__ void k_winner(const int* __restrict__ idx) {
    int i = blockIdx.x * blockDim.x + threadIdx.x;   // grid sized exactly NP
    int y = idx[i * 3 + 1];
    int x = idx[i * 3 + 2];
    x = min(max(x, 0), 143);
    y = min(max(y, 0), 143);
    int b = i / PP;
    int p = i - b * PP;
    atomicMax(&g_winner[b * CELLS + y * XN_ + x], p);
}

__device__ __forceinline__ unsigned long long fma2(unsigned long long a,
                                                   unsigned long long b,
                                                   unsigned long long c) {
    unsigned long long d;
    asm("fma.rn.f32x2 %0, %1, %2, %3;" : "=l"(d) : "l"(a), "l"(b), "l"(c));
    return d;
}
__device__ __forceinline__ unsigned long long splat2(float s) {
    unsigned long long d;
    asm("mov.b64 %0, {%1, %1};" : "=l"(d) : "f"(s));
    return d;
}
__device__ __forceinline__ unsigned long long pack2(float lo, float hi) {
    unsigned long long d;
    asm("mov.b64 %0, {%1, %2};" : "=l"(d) : "f"(lo), "f"(hi));
    return d;
}
__device__ __forceinline__ void unpack2(unsigned long long v, float& lo, float& hi) {
    asm("mov.b64 {%0, %1}, %2;" : "=f"(lo), "=f"(hi) : "l"(v));
}
__device__ __forceinline__ unsigned smaddr(const void* p) {
    unsigned r;
    asm("{ .reg .u64 t; cvta.to.shared.u64 t, %1; cvt.u32.u64 %0, t; }"
        : "=r"(r) : "l"(p));
    return r;
}
// Copy one 1152-byte pillar global->shared via cp.async (72 x 16B chunks).
__device__ __forceinline__ void cp_pillar(unsigned sbase, const float* g, int lane) {
    asm volatile("cp.async.cg.shared.global [%0], [%1], 16;"
                 :: "r"(sbase + lane * 16), "l"(g + lane * 4));
    asm volatile("cp.async.cg.shared.global [%0], [%1], 16;"
                 :: "r"(sbase + (lane + 32) * 16), "l"(g + (lane + 32) * 4));
    if (lane < 8)
        asm volatile("cp.async.cg.shared.global [%0], [%1], 16;"
                     :: "r"(sbase + (lane + 64) * 16), "l"(g + (lane + 64) * 4));
}

// Persistent kernel over the CELL space. One warp per cell (grid-stride);
// empty cells (winner == -1) cost ~1 uniform LDG and skip.
// Lane = (cg, mg): cg = lane>>2 owns channels [8cg, 8cg+8),
//                  mg = lane&3  owns m-points  [8mg, 8mg+8).
// Output goes to g_feat channel-major: warp writes 256 CONTIGUOUS bytes
// (1 STG.64/lane, 2 wavefronts) instead of 64 scattered lines.
__global__ void __launch_bounds__(256, 2) k_compute(
    const float* __restrict__ pillars,
    const float* __restrict__ cw,
    const float* __restrict__ gamma,
    const float* __restrict__ beta,
    const float* __restrict__ mean,
    const float* __restrict__ var)
{
    __shared__ __align__(16) float sm[8][2][288];
    const int wlocal = threadIdx.x >> 5;
    const int lane   = threadIdx.x & 31;
    const int cg     = lane >> 2;
    const int mg     = lane & 3;

    // Per-warp constants (loaded once): wp[f][cp] = (w[8cg+2cp][f], w[8cg+2cp+1][f])
    unsigned long long wp[9][4];
    #pragma unroll
    for (int cp = 0; cp < 4; cp++) {
        const float* w0 = cw + (cg * 8 + 2 * cp) * 9;
        #pragma unroll
        for (int f = 0; f < 9; f++)
            wp[f][cp] = pack2(w0[f], w0[9 + f]);
    }
    const int cs = cg * 8 + mg * 2;   // channels this lane stores
    const float s0 = gamma[cs]     * rsqrtf(var[cs]     + 1e-5f);
    const float s1 = gamma[cs + 1] * rsqrtf(var[cs + 1] + 1e-5f);
    const float b0 = beta[cs]     - mean[cs]     * s0;
    const float b1 = beta[cs + 1] - mean[cs + 1] * s1;

    unsigned sbuf0 = smaddr(&sm[wlocal][0][0]);
    unsigned sbuf1 = smaddr(&sm[wlocal][1][0]);

    int cell = (blockIdx.x * blockDim.x + threadIdx.x) >> 5;
    if (cell >= NC) return;

    int wcur = g_winner[cell];
    if (wcur >= 0)
        cp_pillar(sbuf0, pillars + ((size_t)(cell / CELLS) * PP + wcur) * 288, lane);
    asm volatile("cp.async.commit_group;");
    int pb = 0;

    for (; cell < NC; cell += NWARPS) {
        __syncwarp();   // all lanes aligned before buffer pb may be refilled

        // Prefetch next cell's winner + pillar into the other buffer
        const int ncell = cell + NWARPS;
        const int wnext = (ncell < NC) ? g_winner[ncell] : -1;
        if (wnext >= 0)
            cp_pillar(pb ? sbuf0 : sbuf1,
                      pillars + ((size_t)(ncell / CELLS) * PP + wnext) * 288, lane);
        asm volatile("cp.async.commit_group;");

        if (wcur >= 0) {
            asm volatile("cp.async.wait_group 1;");   // current buffer ready
            __syncwarp();
            const float* buf = &sm[wlocal][pb][0];

            float mx[8];
            #pragma unroll
            for (int j = 0; j < 8; j++) mx[j] = -3.402823466e38f;

            #pragma unroll
            for (int mi = 0; mi < 8; mi++) {
                const float* xr = buf + (mg * 8 + mi) * 9;
                unsigned long long a0 = 0ull, a1 = 0ull, a2 = 0ull, a3 = 0ull;
                #pragma unroll
                for (int f = 0; f < 9; f++) {
                    unsigned long long xs = splat2(xr[f]);
                    a0 = fma2(xs, wp[f][0], a0);
                    a1 = fma2(xs, wp[f][1], a1);
                    a2 = fma2(xs, wp[f][2], a2);
                    a3 = fma2(xs, wp[f][3], a3);
                }
                float t0, t1;
                unpack2(a0, t0, t1); mx[0] = fmaxf(mx[0], t0); mx[1] = fmaxf(mx[1], t1);
                unpack2(a1, t0, t1); mx[2] = fmaxf(mx[2], t0); mx[3] = fmaxf(mx[3], t1);
                unpack2(a2, t0, t1); mx[4] = fmaxf(mx[4], t0); mx[5] = fmaxf(mx[5], t1);
                unpack2(a3, t0, t1); mx[6] = fmaxf(mx[6], t0); mx[7] = fmaxf(mx[7], t1);
            }

            // Reduce max over the 4 mg lanes (lane = cg*4 + mg)
            #pragma unroll
            for (int j = 0; j < 8; j++) {
                mx[j] = fmaxf(mx[j], __shfl_xor_sync(0xFFFFFFFFu, mx[j], 1));
                mx[j] = fmaxf(mx[j], __shfl_xor_sync(0xFFFFFFFFu, mx[j], 2));
            }

            // BN+ReLU applied once to the raw max (scale>0, monotone => exact)
            const float fA = fmaxf(fmaf(mx[mg * 2],     s0, b0), 0.0f);
            const float fB = fmaxf(fmaf(mx[mg * 2 + 1], s1, b1), 0.0f);
            // Dense channel-major store: warp covers 64 consecutive floats
            reinterpret_cast<float2*>(g_feat + ((size_t)cell << 6))[lane + ((cs & 1) ? 0 : 0)] =
                make_float2(fA, fB);
        }

        wcur = wnext;
        pb ^= 1;
    }
}

// Transpose g_feat [b][cell][c] -> out [b][c][cell], writing zeros for empty
// cells (also replaces the output memset). Tile = 32 cells x 64 channels.
// Reads are warp-uniform per cell (skip empty -> no feat traffic), writes are
// fully coalesced 128B segments.
__global__ void __launch_bounds__(256) k_transpose(float* __restrict__ out) {
    __shared__ float ts[64][33];
    __shared__ int win[32];
    const int t     = threadIdx.x;
    const int b     = blockIdx.y;
    const int cell0 = blockIdx.x * 32;

    if (t < 32) win[t] = g_winner[b * CELLS + cell0 + t];
    __syncthreads();

    // Read phase: c = t&63 (coalesced 256B per cell row), cl = t>>6 (+4 per pass)
    {
        const int c = t & 63;
        #pragma unroll
        for (int k = 0; k < 8; k++) {
            const int cl = (t >> 6) + k * 4;
            float v = 0.0f;
            if (win[cl] >= 0)
                v = g_feat[(((size_t)(b * CELLS + cell0 + cl)) << 6) + c];
            ts[c][cl] = v;
        }
    }
    __syncthreads();

    // Write phase: cl = t&31 (coalesced 128B), c = t>>5 (+8 per pass)
    {
        const int cl = t & 31;
        #pragma unroll
        for (int k = 0; k < 8; k++) {
            const int c = (t >> 5) + k * 8;
            out[((size_t)(b * 64 + c)) * CELLS + cell0 + cl] = ts[c][cl];
        }
    }
}

extern "C" void kernel_launch(void* const* d_in, const int* in_sizes, int n_in,
                              void* d_out, int out_size) {
    const float* pillars = (const float*)d_in[0];
    const int*   idx     = (const int*)d_in[1];
    const float* cw      = (const float*)d_in[2];
    const float* gamma   = (const float*)d_in[3];
    const float* beta    = (const float*)d_in[4];
    const float* mean    = (const float*)d_in[5];
    const float* var     = (const float*)d_in[6];
    float* out = (float*)d_out;

    void* winner_ptr = nullptr;
    cudaGetSymbolAddress(&winner_ptr, g_winner);

    cudaMemsetAsync(winner_ptr, 0xFF, sizeof(int) * NC, 0);  // -1
    k_winner<<<NP / 256, 256>>>(idx);
    k_compute<<<NBLK, 256>>>(pillars, cw, gamma, beta, mean, var);
    k_transpose<<<dim3(CELLS / 32, BB), 256>>>(out);
}